// round 16
// baseline (speedup 1.0000x reference)
#include <cuda_runtime.h>
#include <cuda_fp16.h>
#include <cstdint>
#include <math.h>

#define B_   32
#define S_   512
#define IN_  64
#define D_   512
#define H_   8
#define L_   4
#define FF_  2048
#define TOK_ (B_ * S_)   // 16384

// ---------------- scratch (device globals; no allocation allowed) ----------------
__device__ __align__(16) float  g_x[TOK_ * D_];          // fp32 residual stream
__device__ __align__(16) __half g_xh[TOK_ * D_];         // fp16 copy (GEMM input)
__device__ __align__(16) __half g_qkvh[TOK_ * 3 * D_];   // fp16 qkv (attention input)
__device__ __align__(16) __half g_ctxh[TOK_ * D_];       // fp16 ctx (out_proj input)
__device__ __align__(16) float  g_tmp[TOK_ * D_];        // fp32 GEMM outputs -> LN
__device__ __align__(16) __half g_ffh[TOK_ * FF_];       // fp16 GELU out (ff2 input)
__device__ __align__(16) float  g_pool[B_ * 2 * D_];
__device__ __align__(16) float  g_head[B_ * D_];
__device__ __align__(16) float  g_pe[S_ * D_];
// fp16 weights: [in_proj | out_proj | ff1 | ff2]
#define WB_IN  0
#define WB_OUT (WB_IN  + L_ * 3 * D_ * D_)
#define WB_FF1 (WB_OUT + L_ * D_ * D_)
#define WB_FF2 (WB_FF1 + L_ * FF_ * D_)
#define WB_TOT (WB_FF2 + L_ * D_ * FF_)
__device__ __align__(16) __half g_wbufh[WB_TOT];

__device__ __forceinline__ float gelu_exact(float v) {
    return 0.5f * v * (1.0f + erff(v * 0.7071067811865475f));
}
__device__ __forceinline__ float fast_exp(float x) {
    float y = x * 1.442695041f;
    float z = y + 12582912.f;
    float k = z - 12582912.f;
    float f = y - k;
    float p = 1.3333558e-3f;
    p = fmaf(p, f, 9.6181291e-3f);
    p = fmaf(p, f, 5.5504109e-2f);
    p = fmaf(p, f, 2.4022651e-1f);
    p = fmaf(p, f, 6.9314718e-1f);
    p = fmaf(p, f, 1.0f);
    int ki = (__float_as_int(z) - 0x4B400000) << 23;
    return __int_as_float(__float_as_int(p) + ki);
}
__device__ __forceinline__ uint32_t smem_u32(const void* p) {
    uint32_t a;
    asm("{ .reg .u64 t; cvta.to.shared.u64 t, %1; cvt.u32.u64 %0, t; }" : "=r"(a) : "l"(p));
    return a;
}
// non-volatile: lets compiler interleave HMMA with next ldmatrix
__device__ __forceinline__ void mma_f16(float* c, const uint32_t* a, const uint32_t* b) {
    asm("mma.sync.aligned.m16n8k16.row.col.f32.f16.f16.f32 "
        "{%0,%1,%2,%3}, {%4,%5,%6,%7}, {%8,%9}, {%0,%1,%2,%3};"
        : "+f"(c[0]), "+f"(c[1]), "+f"(c[2]), "+f"(c[3])
        : "r"(a[0]), "r"(a[1]), "r"(a[2]), "r"(a[3]), "r"(b[0]), "r"(b[1]));
}
#define LDSM_X4(r0, r1, r2, r3, addr) \
    asm volatile("ldmatrix.sync.aligned.m8n8.x4.shared.b16 {%0,%1,%2,%3}, [%4];" \
        : "=r"(r0), "=r"(r1), "=r"(r2), "=r"(r3) : "r"(addr))
#define LDSM_X4_T(r0, r1, r2, r3, addr) \
    asm volatile("ldmatrix.sync.aligned.m8n8.x4.trans.shared.b16 {%0,%1,%2,%3}, [%4];" \
        : "=r"(r0), "=r"(r1), "=r"(r2), "=r"(r3) : "r"(addr))

// ---------------- fp16 conversion of ALL weights (one launch) ----------------
__global__ __launch_bounds__(256)
void round_all(const float* __restrict__ w_in, const float* __restrict__ w_out,
               const float* __restrict__ w_ff1, const float* __restrict__ w_ff2,
               __half* __restrict__ dst)
{
    const int i = (blockIdx.x * 256 + threadIdx.x) * 4;
    if (i >= WB_TOT) return;
    const float* src;
    int off;
    if (i < WB_OUT)      { src = w_in;  off = i - WB_IN;  }
    else if (i < WB_FF1) { src = w_out; off = i - WB_OUT; }
    else if (i < WB_FF2) { src = w_ff1; off = i - WB_FF1; }
    else                 { src = w_ff2; off = i - WB_FF2; }
    const float4 v = *(const float4*)(src + off);
    __half2* d = (__half2*)(dst + i);
    d[0] = __floats2half2_rn(v.x, v.y);
    d[1] = __floats2half2_rn(v.z, v.w);
}

// ---------------- positional encoding table (once per replay) ----------------
__global__ __launch_bounds__(256)
void pe_init(float* __restrict__ pe)
{
    const int i = blockIdx.x * 256 + threadIdx.x;
    const int s = i >> 9;
    const int d = i & (D_ - 1);
    const float freq = expf(-9.210340371976184f * (float)(d & ~1) / (float)D_);
    const float ang = (float)s * freq;
    pe[i] = (d & 1) ? cosf(ang) : sinf(ang);
}

// ======================= fp16 mma.sync GEMM =======================
// C[M,N] = act(A[M,K] * W[N,K]^T + bias), A/W fp16, accum fp32.
// 128x128x32 CTA tile, 256 thr = 8 warps in 2(M)x4(N), warp tile 64x32.
// 2 CTAs/SM -> 16 warps/SM. 3-buffer/2-prefetch cp.async, 1 barrier/chunk.
#define MH_RS     40                      // halves per row (32 data + 8 pad)
#define MH_TILEB  (128 * MH_RS * 2)       // 10240 B per operand
#define MH_STAGE  (2 * MH_TILEB)          // 20480 B per stage
#define MH_NST    3
#define MH_SMEM   (MH_NST * MH_STAGE)     // 61440 B

__device__ __forceinline__ void mh_cp_issue(
    const __half* __restrict__ A, const __half* __restrict__ W,
    uint32_t sbase, int stage, int m0, int n0, int K, int k0, int tid)
{
    const uint32_t as = sbase + stage * MH_STAGE;
    const uint32_t bs = as + MH_TILEB;
#pragma unroll
    for (int i = 0; i < 2; i++) {
        const int idx = i * 256 + tid;      // 0..511
        const int row = idx >> 2;
        const int q = idx & 3;
        const uint32_t so = (uint32_t)(row * (MH_RS * 2) + q * 16);
        const __half* ga = A + (size_t)(m0 + row) * K + k0 + q * 8;
        const __half* gw = W + (size_t)(n0 + row) * K + k0 + q * 8;
        asm volatile("cp.async.cg.shared.global [%0], [%1], 16;" :: "r"(as + so), "l"(ga));
        asm volatile("cp.async.cg.shared.global [%0], [%1], 16;" :: "r"(bs + so), "l"(gw));
    }
    asm volatile("cp.async.commit_group;" ::: "memory");
}

// ACT: 0=none, 1=exact GELU.  OUT: 0=fp32, 2=fp16
template <int ACT, int OUT>
__global__ __launch_bounds__(256, 2)
void gemm_h(const __half* __restrict__ A, const __half* __restrict__ W,
            const float* __restrict__ bias, float* __restrict__ C,
            __half* __restrict__ CH, int M, int N, int K)
{
    extern __shared__ char smem[];
    const uint32_t sbase = smem_u32(smem);
    const int tid = threadIdx.x;
    const int lane = tid & 31, wid = tid >> 5;
    const int g = lane >> 2, t4 = lane & 3;
    const int wm = wid & 1;          // M half (64 rows)
    const int wn = wid >> 1;         // N quarter (32 cols), 0..3
    const int m0 = blockIdx.y * 128, n0 = blockIdx.x * 128;

    const uint32_t a_lane = (uint32_t)((wm * 64 + (lane & 7) + (lane & 8)) * MH_RS
                                       + ((lane & 16) >> 1));
    const uint32_t b_lane = (uint32_t)((wn * 32 + ((lane & 16) >> 1) + (lane & 7)) * MH_RS
                                       + (lane & 8));

    float acc[4][4][4];
#pragma unroll
    for (int mt = 0; mt < 4; mt++)
#pragma unroll
        for (int nt = 0; nt < 4; nt++)
#pragma unroll
            for (int j = 0; j < 4; j++) acc[mt][nt][j] = 0.f;

    const int nch = K >> 5;
    mh_cp_issue(A, W, sbase, 0, m0, n0, K, 0, tid);
    mh_cp_issue(A, W, sbase, 1, m0, n0, K, 32, tid);

    int cur = 0;
    for (int c = 0; c < nch; c++) {
        if (c + 1 < nch)
            asm volatile("cp.async.wait_group 1;" ::: "memory");
        else
            asm volatile("cp.async.wait_group 0;" ::: "memory");
        __syncthreads();

        const uint32_t a_base = sbase + cur * MH_STAGE + a_lane * 2;
        const uint32_t b_base = sbase + cur * MH_STAGE + MH_TILEB + b_lane * 2;

#pragma unroll
        for (int ks = 0; ks < 2; ks++) {
            uint32_t afr[4][4];
#pragma unroll
            for (int mt = 0; mt < 4; mt++)
                LDSM_X4(afr[mt][0], afr[mt][1], afr[mt][2], afr[mt][3],
                        a_base + (uint32_t)(mt * 16 * MH_RS + ks * 16) * 2);
            uint32_t bfr[4][2];
#pragma unroll
            for (int p = 0; p < 2; p++)
                LDSM_X4(bfr[2 * p][0], bfr[2 * p][1], bfr[2 * p + 1][0], bfr[2 * p + 1][1],
                        b_base + (uint32_t)(p * 16 * MH_RS + ks * 16) * 2);
#pragma unroll
            for (int mt = 0; mt < 4; mt++)
#pragma unroll
                for (int nt = 0; nt < 4; nt++)
                    mma_f16(acc[mt][nt], afr[mt], bfr[nt]);
        }
        if (c + 2 < nch) {
            int tgt = cur + 2; if (tgt >= 3) tgt -= 3;
            mh_cp_issue(A, W, sbase, tgt, m0, n0, K, (c + 2) * 32, tid);
        }
        cur = (cur == 2) ? 0 : cur + 1;
    }

#pragma unroll
    for (int mt = 0; mt < 4; mt++) {
        const int r0 = m0 + wm * 64 + mt * 16 + g;
#pragma unroll
        for (int nt = 0; nt < 4; nt++) {
            const int cb = n0 + wn * 32 + nt * 8 + 2 * t4;
            const float b0 = bias[cb], b1 = bias[cb + 1];
            float v0 = acc[mt][nt][0] + b0;
            float v1 = acc[mt][nt][1] + b1;
            float v2 = acc[mt][nt][2] + b0;
            float v3 = acc[mt][nt][3] + b1;
            if (ACT == 1) {
                v0 = gelu_exact(v0); v1 = gelu_exact(v1);
                v2 = gelu_exact(v2); v3 = gelu_exact(v3);
            }
            if (OUT == 2) {
                *(__half2*)&CH[(size_t)r0 * N + cb]       = __floats2half2_rn(v0, v1);
                *(__half2*)&CH[(size_t)(r0 + 8) * N + cb] = __floats2half2_rn(v2, v3);
            } else {
                *(float2*)&C[(size_t)r0 * N + cb]       = make_float2(v0, v1);
                *(float2*)&C[(size_t)(r0 + 8) * N + cb] = make_float2(v2, v3);
            }
        }
    }
}

// ======================= fused attention (fp16 mma) =======================
// block = (q-tile 32) x (b*H+h). 256 threads (8 warps), 2 CTAs/SM.
#define FA_QS_B   0
#define FA_SC_B   4608
#define FA_KV_B   70656
#define FA_SMEM_BYTES 89088
#define FA_SS 516      // fp32 score stride (floats)
#define FA_PH_B 2064   // fp16 prob row stride (bytes)

__global__ __launch_bounds__(256, 2)
void fused_attn(const __half* __restrict__ qkv, float* __restrict__ probs,
                __half* __restrict__ ctxh)
{
    extern __shared__ char smem[];
    const uint32_t sbase = smem_u32(smem);
    __half* qs = (__half*)(smem + FA_QS_B);
    float*  sc = (float*)(smem + FA_SC_B);
    __half* kv = (__half*)(smem + FA_KV_B);

    const int tid = threadIdx.x;
    const int lane = tid & 31, wid = tid >> 5;
    const int g = lane >> 2, t4 = lane & 3;
    const int q0 = blockIdx.x * 32;
    const int bh = blockIdx.y;
    const int b = bh >> 3, h = bh & 7;
    const int wm = wid & 1;
    const int wn = wid >> 1;

    const uint32_t qa_addr = sbase + FA_QS_B +
        (uint32_t)((wm * 16 + (lane & 7) + (lane & 8)) * 72 + ((lane & 16) >> 1)) * 2;
    const uint32_t kb_addr = sbase + FA_KV_B +
        (uint32_t)((wn * 32 + ((lane & 16) >> 1) + (lane & 7)) * 72 + (lane & 8)) * 2;
    const uint32_t pa_addr = sbase + FA_SC_B +
        (uint32_t)(wm * 16 + (lane & 7) + (lane & 8)) * FA_PH_B + (uint32_t)((lane & 16) >> 1) * 2;
    const uint32_t vb_addr = sbase + FA_KV_B +
        (uint32_t)((lane & 15) * 72 + wn * 16 + ((lane & 16) >> 1)) * 2;

    {
        const int r = tid >> 3;
        const int d0 = (tid & 7) * 8;
        const __half* src = qkv + (size_t)(b * S_ + q0 + r) * 1536 + h * 64 + d0;
        const __half2 scale = __floats2half2_rn(0.125f, 0.125f);
        const uint2 raw0 = *(const uint2*)src;
        const uint2 raw1 = *(const uint2*)(src + 4);
        __half2* dst = (__half2*)(qs + r * 72 + d0);
        dst[0] = __hmul2(*(const __half2*)&raw0.x, scale);
        dst[1] = __hmul2(*(const __half2*)&raw0.y, scale);
        dst[2] = __hmul2(*(const __half2*)&raw1.x, scale);
        dst[3] = __hmul2(*(const __half2*)&raw1.y, scale);
    }

    for (int kt = 0; kt < 4; kt++) {
        __syncthreads();
#pragma unroll
        for (int i = 0; i < 4; i++) {
            const int idx = i * 256 + tid;
            const int r = idx >> 3;
            const int d0 = (idx & 7) * 8;
            const __half* src = qkv + (size_t)(b * S_ + kt * 128 + r) * 1536 + D_ + h * 64 + d0;
            *(uint4*)(kv + r * 72 + d0) = *(const uint4*)src;
        }
        __syncthreads();

        float acc[4][4];
#pragma unroll
        for (int nt = 0; nt < 4; nt++)
#pragma unroll
            for (int j = 0; j < 4; j++) acc[nt][j] = 0.f;

#pragma unroll
        for (int ks = 0; ks < 4; ks++) {
            uint32_t afr[4];
            LDSM_X4(afr[0], afr[1], afr[2], afr[3], qa_addr + (uint32_t)(ks * 16) * 2);
            uint32_t bfr[4][2];
#pragma unroll
            for (int p = 0; p < 2; p++)
                LDSM_X4(bfr[2 * p][0], bfr[2 * p][1], bfr[2 * p + 1][0], bfr[2 * p + 1][1],
                        kb_addr + (uint32_t)(p * 16 * 72 + ks * 16) * 2);
#pragma unroll
            for (int nt = 0; nt < 4; nt++)
                mma_f16(acc[nt], afr, bfr[nt]);
        }
#pragma unroll
        for (int nt = 0; nt < 4; nt++) {
            const int col = kt * 128 + wn * 32 + nt * 8 + 2 * t4;
            const int row = wm * 16 + g;
            *(float2*)&sc[row * FA_SS + col]       = make_float2(acc[nt][0], acc[nt][1]);
            *(float2*)&sc[(row + 8) * FA_SS + col] = make_float2(acc[nt][2], acc[nt][3]);
        }
    }
    __syncthreads();

#pragma unroll
    for (int rr = 0; rr < 4; rr++) {
        const int row = wid * 4 + rr;
        float vals[16];
        float sum = 0.f;
#pragma unroll
        for (int t = 0; t < 4; t++) {
            const float4 v = *(const float4*)&sc[row * FA_SS + lane * 4 + t * 128];
            vals[t * 4 + 0] = fast_exp(v.x);
            vals[t * 4 + 1] = fast_exp(v.y);
            vals[t * 4 + 2] = fast_exp(v.z);
            vals[t * 4 + 3] = fast_exp(v.w);
            sum += vals[t * 4 + 0] + vals[t * 4 + 1] + vals[t * 4 + 2] + vals[t * 4 + 3];
        }
#pragma unroll
        for (int o = 16; o > 0; o >>= 1)
            sum += __shfl_xor_sync(0xFFFFFFFFu, sum, o);
        const float inv = 1.f / sum;
        float* prow = probs + ((size_t)bh * S_ + q0 + row) * S_;
        __half* phrow = (__half*)((char*)sc + row * FA_PH_B);
#pragma unroll
        for (int t = 0; t < 4; t++) {
            const int c = lane * 4 + t * 128;
            const __half2 h0 = __floats2half2_rn(vals[t * 4 + 0] * inv, vals[t * 4 + 1] * inv);
            const __half2 h1 = __floats2half2_rn(vals[t * 4 + 2] * inv, vals[t * 4 + 3] * inv);
            *(__half2*)&phrow[c]     = h0;
            *(__half2*)&phrow[c + 2] = h1;
            float4 o;
            o.x = __half2float(__low2half(h0));
            o.y = __half2float(__high2half(h0));
            o.z = __half2float(__low2half(h1));
            o.w = __half2float(__high2half(h1));
            *(float4*)&prow[c] = o;
        }
    }

    float pacc[2][4];
#pragma unroll
    for (int nt = 0; nt < 2; nt++)
#pragma unroll
        for (int j = 0; j < 4; j++) pacc[nt][j] = 0.f;

    for (int vt = 0; vt < 4; vt++) {
        __syncthreads();
#pragma unroll
        for (int i = 0; i < 4; i++) {
            const int idx = i * 256 + tid;
            const int r = idx >> 3;
            const int d0 = (idx & 7) * 8;
            const __half* src = qkv + (size_t)(b * S_ + vt * 128 + r) * 1536 + 2 * D_ + h * 64 + d0;
            *(uint4*)(kv + r * 72 + d0) = *(const uint4*)src;
        }
        __syncthreads();

#pragma unroll
        for (int ks = 0; ks < 8; ks++) {
            uint32_t afr[4];
            LDSM_X4(afr[0], afr[1], afr[2], afr[3],
                    pa_addr + (uint32_t)(vt * 128 + ks * 16) * 2);
            uint32_t bfr[2][2];
            LDSM_X4_T(bfr[0][0], bfr[0][1], bfr[1][0], bfr[1][1],
                      vb_addr + (uint32_t)(ks * 16 * 72) * 2);
            mma_f16(pacc[0], afr, bfr[0]);
            mma_f16(pacc[1], afr, bfr[1]);
        }
    }

#pragma unroll
    for (int nt = 0; nt < 2; nt++) {
        const int row = b * S_ + q0 + wm * 16 + g;
        const int col = h * 64 + wn * 16 + nt * 8 + 2 * t4;
        *(__half2*)&ctxh[(size_t)row * D_ + col] =
            __floats2half2_rn(pacc[nt][0], pacc[nt][1]);
        *(__half2*)&ctxh[(size_t)(row + 8) * D_ + col] =
            __floats2half2_rn(pacc[nt][2], pacc[nt][3]);
    }
}

// ---------------- SIMT GEMM (input proj / head1) ----------------
template <int ACT>
__global__ __launch_bounds__(256)
void gemm_kernel(const float* __restrict__ A, const float* __restrict__ W,
                 const float* __restrict__ bias, float* __restrict__ C,
                 __half* __restrict__ CH,
                 int M, int N, int K, const float* __restrict__ pe)
{
    __shared__ __align__(16) float As[8][128];
    __shared__ __align__(16) float Ws[8][128];

    const int tid = threadIdx.x;
    const int tx = tid & 15;
    const int ty = tid >> 4;
    const int m0 = blockIdx.y * 128;
    const int n0 = blockIdx.x * 128;

    float acc[2][2][4][4];
#pragma unroll
    for (int p = 0; p < 2; p++)
#pragma unroll
        for (int q = 0; q < 2; q++)
#pragma unroll
            for (int i = 0; i < 4; i++)
#pragma unroll
                for (int j = 0; j < 4; j++) acc[p][q][i][j] = 0.f;

    const int lr = tid >> 1;
    const int lk = (tid & 1) * 4;
    const float* Ag = A + (size_t)(m0 + lr) * K + lk;
    const float* Wg = W + (size_t)(n0 + lr) * K + lk;
    const bool aval = (m0 + lr) < M;

    for (int k0 = 0; k0 < K; k0 += 8) {
        float4 av = make_float4(0.f, 0.f, 0.f, 0.f);
        if (aval) av = *(const float4*)(Ag + k0);
        const float4 wv = *(const float4*)(Wg + k0);
        __syncthreads();
        As[lk + 0][lr] = av.x; As[lk + 1][lr] = av.y;
        As[lk + 2][lr] = av.z; As[lk + 3][lr] = av.w;
        Ws[lk + 0][lr] = wv.x; Ws[lk + 1][lr] = wv.y;
        Ws[lk + 2][lr] = wv.z; Ws[lk + 3][lr] = wv.w;
        __syncthreads();
#pragma unroll
        for (int kk = 0; kk < 8; kk++) {
            const float4 a0 = *(const float4*)&As[kk][ty * 4];
            const float4 a1 = *(const float4*)&As[kk][64 + ty * 4];
            const float4 b0 = *(const float4*)&Ws[kk][tx * 4];
            const float4 b1 = *(const float4*)&Ws[kk][64 + tx * 4];
            const float ar[2][4] = {{a0.x, a0.y, a0.z, a0.w}, {a1.x, a1.y, a1.z, a1.w}};
            const float br[2][4] = {{b0.x, b0.y, b0.z, b0.w}, {b1.x, b1.y, b1.z, b1.w}};
#pragma unroll
            for (int p = 0; p < 2; p++)
#pragma unroll
                for (int q = 0; q < 2; q++)
#pragma unroll
                    for (int i = 0; i < 4; i++)
#pragma unroll
                        for (int j = 0; j < 4; j++)
                            acc[p][q][i][j] += ar[p][i] * br[q][j];
        }
    }

#pragma unroll
    for (int p = 0; p < 2; p++) {
#pragma unroll
        for (int i = 0; i < 4; i++) {
            const int m = m0 + p * 64 + ty * 4 + i;
            if (m >= M) continue;
#pragma unroll
            for (int q = 0; q < 2; q++) {
                const int c = n0 + q * 64 + tx * 4;
                float4 o;
                float* po = &o.x;
#pragma unroll
                for (int j = 0; j < 4; j++) {
                    float v = acc[p][q][i][j] + bias[c + j];
                    if (ACT == 1) {
                        v = gelu_exact(v);
                    } else if (ACT == 2) {
                        v += pe[(m & (S_ - 1)) * D_ + c + j];
                    }
                    po[j] = v;
                }
                *(float4*)&C[(size_t)m * N + c] = o;
                if (ACT == 2) {
                    __half2* hd = (__half2*)&CH[(size_t)m * N + c];
                    hd[0] = __floats2half2_rn(o.x, o.y);
                    hd[1] = __floats2half2_rn(o.z, o.w);
                }
            }
        }
    }
}

// ---------------- fused residual-add + LayerNorm (fp32 + fp16 outputs) ----------------
__global__ __launch_bounds__(128)
void ln_kernel(const float* __restrict__ x, const float* __restrict__ add,
               const float* __restrict__ w, const float* __restrict__ bvec,
               float* __restrict__ out, __half* __restrict__ outh)
{
    const int row = blockIdx.x;
    const int tid = threadIdx.x;
    const float* xr = x + (size_t)row * D_;
    const float* ar = add + (size_t)row * D_;
    float v[4];
    float s = 0.f;
#pragma unroll
    for (int i = 0; i < 4; i++) {
        const int c = tid + i * 128;
        v[i] = xr[c] + ar[c];
        s += v[i];
    }
    __shared__ float red[4];
#pragma unroll
    for (int o = 16; o > 0; o >>= 1) s += __shfl_xor_sync(0xFFFFFFFFu, s, o);
    if ((tid & 31) == 0) red[tid >> 5] = s;
    __syncthreads();
    const float mean = (red[0] + red[1] + red[2] + red[3]) * (1.f / 512.f);
    float vs = 0.f;
#pragma unroll
    for (int i = 0; i < 4; i++) {
        const float d = v[i] - mean;
        vs += d * d;
    }
    __syncthreads();
#pragma unroll
    for (int o = 16; o > 0; o >>= 1) vs += __shfl_xor_sync(0xFFFFFFFFu, vs, o);
    if ((tid & 31) == 0) red[tid >> 5] = vs;
    __syncthreads();
    const float rstd = rsqrtf((red[0] + red[1] + red[2] + red[3]) * (1.f / 512.f) + 1e-5f);
    float* orow = out + (size_t)row * D_;
    __half* hrow = outh + (size_t)row * D_;
#pragma unroll
    for (int i = 0; i < 4; i++) {
        const int c = tid + i * 128;
        const float val = (v[i] - mean) * rstd * w[c] + bvec[c];
        orow[c] = val;
        hrow[c] = __float2half_rn(val);
    }
}

// ---------------- mean+max pooling over sequence ----------------
__global__ __launch_bounds__(512)
void pool_kernel(const float* __restrict__ x, float* __restrict__ pool)
{
    const int b = blockIdx.x, d = threadIdx.x;
    float s = 0.f, m = -1e30f;
    for (int t = 0; t < S_; t++) {
        const float v = x[(size_t)(b * S_ + t) * D_ + d];
        s += v;
        m = fmaxf(m, v);
    }
    pool[b * (2 * D_) + d] = s * (1.f / 512.f);
    pool[b * (2 * D_) + D_ + d] = m;
}

// ---------------- final head ----------------
__global__ __launch_bounds__(128)
void head2_kernel(const float* __restrict__ h, const float* __restrict__ w,
                  const float* __restrict__ bb, float* __restrict__ out)
{
    const int b = blockIdx.x, tid = threadIdx.x;
    float s = 0.f;
    for (int c = tid; c < D_; c += 128) s += h[(size_t)b * D_ + c] * w[c];
    __shared__ float red[4];
#pragma unroll
    for (int o = 16; o > 0; o >>= 1) s += __shfl_xor_sync(0xFFFFFFFFu, s, o);
    if ((tid & 31) == 0) red[tid >> 5] = s;
    __syncthreads();
    if (tid == 0) out[b] = red[0] + red[1] + red[2] + red[3] + bb[0];
}

// ---------------- launch ----------------
extern "C" void kernel_launch(void* const* d_in, const int* in_sizes, int n_in,
                              void* d_out, int out_size)
{
    const float* x_in = (const float*)d_in[0];
    const float* w_in = (const float*)d_in[1];
    const float* b_in = (const float*)d_in[2];
    const float* inpw = (const float*)d_in[3];
    const float* inpb = (const float*)d_in[4];
    const float* outw = (const float*)d_in[5];
    const float* outb = (const float*)d_in[6];
    const float* ln1w = (const float*)d_in[7];
    const float* ln1b = (const float*)d_in[8];
    const float* ln2w = (const float*)d_in[9];
    const float* ln2b = (const float*)d_in[10];
    const float* ff1w = (const float*)d_in[11];
    const float* ff1b = (const float*)d_in[12];
    const float* ff2w = (const float*)d_in[13];
    const float* ff2b = (const float*)d_in[14];
    const float* h1w  = (const float*)d_in[15];
    const float* h1b  = (const float*)d_in[16];
    const float* h2w  = (const float*)d_in[17];
    const float* h2b  = (const float*)d_in[18];

    float* out  = (float*)d_out;
    float* attn = out + 32;   // [L,B,H,S,S] follows the [B,1] output

    float *px, *ptmp, *ppool, *phead, *ppe;
    __half *pxh, *pqkvh, *pctxh, *pffh, *pwbh;
    cudaGetSymbolAddress((void**)&px,    g_x);
    cudaGetSymbolAddress((void**)&pxh,   g_xh);
    cudaGetSymbolAddress((void**)&pqkvh, g_qkvh);
    cudaGetSymbolAddress((void**)&pctxh, g_ctxh);
    cudaGetSymbolAddress((void**)&ptmp,  g_tmp);
    cudaGetSymbolAddress((void**)&pffh,  g_ffh);
    cudaGetSymbolAddress((void**)&ppool, g_pool);
    cudaGetSymbolAddress((void**)&phead, g_head);
    cudaGetSymbolAddress((void**)&pwbh,  g_wbufh);
    cudaGetSymbolAddress((void**)&ppe,   g_pe);

    cudaFuncSetAttribute(gemm_h<0,2>, cudaFuncAttributeMaxDynamicSharedMemorySize, MH_SMEM);
    cudaFuncSetAttribute(gemm_h<0,0>, cudaFuncAttributeMaxDynamicSharedMemorySize, MH_SMEM);
    cudaFuncSetAttribute(gemm_h<1,2>, cudaFuncAttributeMaxDynamicSharedMemorySize, MH_SMEM);
    cudaFuncSetAttribute(fused_attn, cudaFuncAttributeMaxDynamicSharedMemorySize, FA_SMEM_BYTES);

    const dim3 blk(256);
    const dim3 mblk(256);

    // per-replay setup: fp16 weights + PE table
    round_all<<<(WB_TOT + 1023) / 1024, 256>>>(inpw, outw, ff1w, ff2w, pwbh);
    pe_init<<<(S_ * D_) / 256, 256>>>(ppe);

    // input projection + PE (SIMT; fp32 residual + fp16 GEMM copy)
    gemm_kernel<2><<<dim3(D_ / 128, TOK_ / 128), blk>>>(
        x_in, w_in, b_in, px, pxh, TOK_, D_, IN_, ppe);

    for (int l = 0; l < L_; l++) {
        // QKV projection (fp16 in, fp16 out -> attention)
        gemm_h<0,2><<<dim3((3 * D_) / 128, TOK_ / 128), mblk, MH_SMEM>>>(
            pxh, pwbh + WB_IN + (size_t)l * 3 * D_ * D_, inpb + l * 3 * D_,
            nullptr, pqkvh, TOK_, 3 * D_, D_);

        float* attn_l = attn + (size_t)l * B_ * H_ * S_ * S_;

        // fused scores + softmax + probs-out + P@V (all fp16 mma)
        fused_attn<<<dim3(S_ / 32, B_ * H_), blk, FA_SMEM_BYTES>>>(pqkvh, attn_l, pctxh);

        // output projection (fp16 in, fp32 out -> LN)
        gemm_h<0,0><<<dim3(D_ / 128, TOK_ / 128), mblk, MH_SMEM>>>(
            pctxh, pwbh + WB_OUT + (size_t)l * D_ * D_, outb + l * D_,
            ptmp, nullptr, TOK_, D_, D_);

        ln_kernel<<<TOK_, 128>>>(px, ptmp, ln1w + l * D_, ln1b + l * D_, px, pxh);

        // ff1 + GELU (fp16 in, fp16 out -> ff2)
        gemm_h<1,2><<<dim3(FF_ / 128, TOK_ / 128), mblk, MH_SMEM>>>(
            pxh, pwbh + WB_FF1 + (size_t)l * FF_ * D_, ff1b + l * FF_,
            nullptr, pffh, TOK_, FF_, D_);

        // ff2 (fp16 in, fp32 out -> LN)
        gemm_h<0,0><<<dim3(D_ / 128, TOK_ / 128), mblk, MH_SMEM>>>(
            pffh, pwbh + WB_FF2 + (size_t)l * D_ * FF_, ff2b + l * D_,
            ptmp, nullptr, TOK_, D_, FF_);

        ln_kernel<<<TOK_, 128>>>(px, ptmp, ln2w + l * D_, ln2b + l * D_, px, pxh);
    }

    pool_kernel<<<B_, 512>>>(px, ppool);
    gemm_kernel<1><<<dim3(D_ / 128, 1), blk>>>(
        ppool, h1w, h1b, phead, nullptr, B_, D_, 2 * D_, ppe);
    head2_kernel<<<B_, 128>>>(phead, h2w, h2b, out);
}

// round 17
// speedup vs baseline: 1.0626x; 1.0626x over previous
#include <cuda_runtime.h>
#include <cuda_fp16.h>
#include <cstdint>
#include <math.h>

#define B_   32
#define S_   512
#define IN_  64
#define D_   512
#define H_   8
#define L_   4
#define FF_  2048
#define TOK_ (B_ * S_)   // 16384

// ---------------- scratch (device globals; no allocation allowed) ----------------
__device__ __align__(16) float  g_x[TOK_ * D_];          // fp32 residual stream
__device__ __align__(16) __half g_xh[TOK_ * D_];         // fp16 copy (GEMM input)
__device__ __align__(16) __half g_qkvh[TOK_ * 3 * D_];   // fp16 qkv (attention input)
__device__ __align__(16) __half g_ctxh[TOK_ * D_];       // fp16 ctx (out_proj input)
__device__ __align__(16) float  g_tmp[TOK_ * D_];        // fp32 GEMM outputs -> LN
__device__ __align__(16) __half g_ffh[TOK_ * FF_];       // fp16 GELU out (ff2 input)
__device__ __align__(16) float  g_pool[B_ * 2 * D_];
__device__ __align__(16) float  g_head[B_ * D_];
__device__ __align__(16) float  g_pe[S_ * D_];
// fp16 weights: [in_proj | out_proj | ff1 | ff2]
#define WB_IN  0
#define WB_OUT (WB_IN  + L_ * 3 * D_ * D_)
#define WB_FF1 (WB_OUT + L_ * D_ * D_)
#define WB_FF2 (WB_FF1 + L_ * FF_ * D_)
#define WB_TOT (WB_FF2 + L_ * D_ * FF_)
__device__ __align__(16) __half g_wbufh[WB_TOT];

__device__ __forceinline__ float gelu_exact(float v) {
    return 0.5f * v * (1.0f + erff(v * 0.7071067811865475f));
}
__device__ __forceinline__ float fast_exp(float x) {
    float y = x * 1.442695041f;
    float z = y + 12582912.f;
    float k = z - 12582912.f;
    float f = y - k;
    float p = 1.3333558e-3f;
    p = fmaf(p, f, 9.6181291e-3f);
    p = fmaf(p, f, 5.5504109e-2f);
    p = fmaf(p, f, 2.4022651e-1f);
    p = fmaf(p, f, 6.9314718e-1f);
    p = fmaf(p, f, 1.0f);
    int ki = (__float_as_int(z) - 0x4B400000) << 23;
    return __int_as_float(__float_as_int(p) + ki);
}
__device__ __forceinline__ uint32_t smem_u32(const void* p) {
    uint32_t a;
    asm("{ .reg .u64 t; cvta.to.shared.u64 t, %1; cvt.u32.u64 %0, t; }" : "=r"(a) : "l"(p));
    return a;
}
// non-volatile: lets compiler interleave HMMA with surrounding code
__device__ __forceinline__ void mma_f16(float* c, const uint32_t* a, const uint32_t* b) {
    asm("mma.sync.aligned.m16n8k16.row.col.f32.f16.f16.f32 "
        "{%0,%1,%2,%3}, {%4,%5,%6,%7}, {%8,%9}, {%0,%1,%2,%3};"
        : "+f"(c[0]), "+f"(c[1]), "+f"(c[2]), "+f"(c[3])
        : "r"(a[0]), "r"(a[1]), "r"(a[2]), "r"(a[3]), "r"(b[0]), "r"(b[1]));
}
#define LDSM_X4(r0, r1, r2, r3, addr) \
    asm volatile("ldmatrix.sync.aligned.m8n8.x4.shared.b16 {%0,%1,%2,%3}, [%4];" \
        : "=r"(r0), "=r"(r1), "=r"(r2), "=r"(r3) : "r"(addr))
#define LDSM_X4_T(r0, r1, r2, r3, addr) \
    asm volatile("ldmatrix.sync.aligned.m8n8.x4.trans.shared.b16 {%0,%1,%2,%3}, [%4];" \
        : "=r"(r0), "=r"(r1), "=r"(r2), "=r"(r3) : "r"(addr))

// ---------------- fp16 conversion of ALL weights (one launch) ----------------
__global__ __launch_bounds__(256)
void round_all(const float* __restrict__ w_in, const float* __restrict__ w_out,
               const float* __restrict__ w_ff1, const float* __restrict__ w_ff2,
               __half* __restrict__ dst)
{
    const int i = (blockIdx.x * 256 + threadIdx.x) * 4;
    if (i >= WB_TOT) return;
    const float* src;
    int off;
    if (i < WB_OUT)      { src = w_in;  off = i - WB_IN;  }
    else if (i < WB_FF1) { src = w_out; off = i - WB_OUT; }
    else if (i < WB_FF2) { src = w_ff1; off = i - WB_FF1; }
    else                 { src = w_ff2; off = i - WB_FF2; }
    const float4 v = *(const float4*)(src + off);
    __half2* d = (__half2*)(dst + i);
    d[0] = __floats2half2_rn(v.x, v.y);
    d[1] = __floats2half2_rn(v.z, v.w);
}

// ---------------- positional encoding table (once per replay) ----------------
__global__ __launch_bounds__(256)
void pe_init(float* __restrict__ pe)
{
    const int i = blockIdx.x * 256 + threadIdx.x;
    const int s = i >> 9;
    const int d = i & (D_ - 1);
    const float freq = expf(-9.210340371976184f * (float)(d & ~1) / (float)D_);
    const float ang = (float)s * freq;
    pe[i] = (d & 1) ? cosf(ang) : sinf(ang);
}

// ======================= fp16 mma.sync GEMM =======================
// C[M,N] = act(A[M,K] * W[N,K]^T + bias), A/W fp16, accum fp32.
// 128x128x32 CTA tile, 128 thr (4 warps 2x2), warp tile 64x64 (R15 shape).
// Inner loop: BOTH k16 steps' fragments loaded before any mma (manual
// pipeline — volatile ldmatrix blocks compiler reordering).
#define MH_RS     40                      // halves per row (32 data + 8 pad)
#define MH_TILEB  (128 * MH_RS * 2)       // 10240 B per operand
#define MH_STAGE  (2 * MH_TILEB)          // 20480 B per stage
#define MH_NST    3
#define MH_SMEM   (MH_NST * MH_STAGE)     // 61440 B

__device__ __forceinline__ void mh_cp_issue(
    const __half* __restrict__ A, const __half* __restrict__ W,
    uint32_t sbase, int stage, int m0, int n0, int K, int k0, int tid)
{
    const uint32_t as = sbase + stage * MH_STAGE;
    const uint32_t bs = as + MH_TILEB;
#pragma unroll
    for (int i = 0; i < 4; i++) {
        const int idx = i * 128 + tid;      // 0..511
        const int row = idx >> 2;
        const int q = idx & 3;
        const uint32_t so = (uint32_t)(row * (MH_RS * 2) + q * 16);
        const __half* ga = A + (size_t)(m0 + row) * K + k0 + q * 8;
        const __half* gw = W + (size_t)(n0 + row) * K + k0 + q * 8;
        asm volatile("cp.async.cg.shared.global [%0], [%1], 16;" :: "r"(as + so), "l"(ga));
        asm volatile("cp.async.cg.shared.global [%0], [%1], 16;" :: "r"(bs + so), "l"(gw));
    }
    asm volatile("cp.async.commit_group;" ::: "memory");
}

// ACT: 0=none, 1=exact GELU.  OUT: 0=fp32, 2=fp16
template <int ACT, int OUT>
__global__ __launch_bounds__(128, 2)
void gemm_h(const __half* __restrict__ A, const __half* __restrict__ W,
            const float* __restrict__ bias, float* __restrict__ C,
            __half* __restrict__ CH, int M, int N, int K)
{
    extern __shared__ char smem[];
    const uint32_t sbase = smem_u32(smem);
    const int tid = threadIdx.x;
    const int lane = tid & 31, wid = tid >> 5;
    const int g = lane >> 2, t4 = lane & 3;
    const int wm = wid & 1;          // M half (64 rows)
    const int wn = wid >> 1;         // N half (64 cols)
    const int m0 = blockIdx.y * 128, n0 = blockIdx.x * 128;

    const uint32_t a_lane = (uint32_t)((wm * 64 + (lane & 7) + (lane & 8)) * MH_RS
                                       + ((lane & 16) >> 1));
    const uint32_t b_lane = (uint32_t)((wn * 64 + ((lane & 16) >> 1) + (lane & 7)) * MH_RS
                                       + (lane & 8));

    float acc[4][8][4];
#pragma unroll
    for (int mt = 0; mt < 4; mt++)
#pragma unroll
        for (int nt = 0; nt < 8; nt++)
#pragma unroll
            for (int j = 0; j < 4; j++) acc[mt][nt][j] = 0.f;

    const int nch = K >> 5;
    mh_cp_issue(A, W, sbase, 0, m0, n0, K, 0, tid);
    mh_cp_issue(A, W, sbase, 1, m0, n0, K, 32, tid);

    int cur = 0;
    for (int c = 0; c < nch; c++) {
        if (c + 1 < nch)
            asm volatile("cp.async.wait_group 1;" ::: "memory");
        else
            asm volatile("cp.async.wait_group 0;" ::: "memory");
        __syncthreads();

        const uint32_t a_base = sbase + cur * MH_STAGE + a_lane * 2;
        const uint32_t b_base = sbase + cur * MH_STAGE + MH_TILEB + b_lane * 2;

        // manual pipeline: all fragment loads for BOTH k16 steps first,
        // then both mma batches (same per-accumulator order as before).
        uint32_t afr[2][4][4];
        uint32_t bfr[2][8][2];
#pragma unroll
        for (int ks = 0; ks < 2; ks++) {
#pragma unroll
            for (int mt = 0; mt < 4; mt++)
                LDSM_X4(afr[ks][mt][0], afr[ks][mt][1], afr[ks][mt][2], afr[ks][mt][3],
                        a_base + (uint32_t)(mt * 16 * MH_RS + ks * 16) * 2);
#pragma unroll
            for (int p = 0; p < 4; p++)
                LDSM_X4(bfr[ks][2 * p][0], bfr[ks][2 * p][1],
                        bfr[ks][2 * p + 1][0], bfr[ks][2 * p + 1][1],
                        b_base + (uint32_t)(p * 16 * MH_RS + ks * 16) * 2);
        }
#pragma unroll
        for (int ks = 0; ks < 2; ks++)
#pragma unroll
            for (int mt = 0; mt < 4; mt++)
#pragma unroll
                for (int nt = 0; nt < 8; nt++)
                    mma_f16(acc[mt][nt], afr[ks][mt], bfr[ks][nt]);

        if (c + 2 < nch) {
            int tgt = cur + 2; if (tgt >= 3) tgt -= 3;
            mh_cp_issue(A, W, sbase, tgt, m0, n0, K, (c + 2) * 32, tid);
        }
        cur = (cur == 2) ? 0 : cur + 1;
    }

#pragma unroll
    for (int mt = 0; mt < 4; mt++) {
        const int r0 = m0 + wm * 64 + mt * 16 + g;
#pragma unroll
        for (int nt = 0; nt < 8; nt++) {
            const int cb = n0 + wn * 64 + nt * 8 + 2 * t4;
            const float b0 = bias[cb], b1 = bias[cb + 1];
            float v0 = acc[mt][nt][0] + b0;
            float v1 = acc[mt][nt][1] + b1;
            float v2 = acc[mt][nt][2] + b0;
            float v3 = acc[mt][nt][3] + b1;
            if (ACT == 1) {
                v0 = gelu_exact(v0); v1 = gelu_exact(v1);
                v2 = gelu_exact(v2); v3 = gelu_exact(v3);
            }
            if (OUT == 2) {
                *(__half2*)&CH[(size_t)r0 * N + cb]       = __floats2half2_rn(v0, v1);
                *(__half2*)&CH[(size_t)(r0 + 8) * N + cb] = __floats2half2_rn(v2, v3);
            } else {
                *(float2*)&C[(size_t)r0 * N + cb]       = make_float2(v0, v1);
                *(float2*)&C[(size_t)(r0 + 8) * N + cb] = make_float2(v2, v3);
            }
        }
    }
}

// ======================= fused attention (fp16 mma) =======================
// block = (q-tile 32) x (b*H+h). 256 threads (8 warps), 2 CTAs/SM.
#define FA_QS_B   0
#define FA_SC_B   4608
#define FA_KV_B   70656
#define FA_SMEM_BYTES 89088
#define FA_SS 516      // fp32 score stride (floats)
#define FA_PH_B 2064   // fp16 prob row stride (bytes)

__global__ __launch_bounds__(256, 2)
void fused_attn(const __half* __restrict__ qkv, float* __restrict__ probs,
                __half* __restrict__ ctxh)
{
    extern __shared__ char smem[];
    const uint32_t sbase = smem_u32(smem);
    __half* qs = (__half*)(smem + FA_QS_B);
    float*  sc = (float*)(smem + FA_SC_B);
    __half* kv = (__half*)(smem + FA_KV_B);

    const int tid = threadIdx.x;
    const int lane = tid & 31, wid = tid >> 5;
    const int g = lane >> 2, t4 = lane & 3;
    const int q0 = blockIdx.x * 32;
    const int bh = blockIdx.y;
    const int b = bh >> 3, h = bh & 7;
    const int wm = wid & 1;
    const int wn = wid >> 1;

    const uint32_t qa_addr = sbase + FA_QS_B +
        (uint32_t)((wm * 16 + (lane & 7) + (lane & 8)) * 72 + ((lane & 16) >> 1)) * 2;
    const uint32_t kb_addr = sbase + FA_KV_B +
        (uint32_t)((wn * 32 + ((lane & 16) >> 1) + (lane & 7)) * 72 + (lane & 8)) * 2;
    const uint32_t pa_addr = sbase + FA_SC_B +
        (uint32_t)(wm * 16 + (lane & 7) + (lane & 8)) * FA_PH_B + (uint32_t)((lane & 16) >> 1) * 2;
    const uint32_t vb_addr = sbase + FA_KV_B +
        (uint32_t)((lane & 15) * 72 + wn * 16 + ((lane & 16) >> 1)) * 2;

    {
        const int r = tid >> 3;
        const int d0 = (tid & 7) * 8;
        const __half* src = qkv + (size_t)(b * S_ + q0 + r) * 1536 + h * 64 + d0;
        const __half2 scale = __floats2half2_rn(0.125f, 0.125f);
        const uint2 raw0 = *(const uint2*)src;
        const uint2 raw1 = *(const uint2*)(src + 4);
        __half2* dst = (__half2*)(qs + r * 72 + d0);
        dst[0] = __hmul2(*(const __half2*)&raw0.x, scale);
        dst[1] = __hmul2(*(const __half2*)&raw0.y, scale);
        dst[2] = __hmul2(*(const __half2*)&raw1.x, scale);
        dst[3] = __hmul2(*(const __half2*)&raw1.y, scale);
    }

    for (int kt = 0; kt < 4; kt++) {
        __syncthreads();
#pragma unroll
        for (int i = 0; i < 4; i++) {
            const int idx = i * 256 + tid;
            const int r = idx >> 3;
            const int d0 = (idx & 7) * 8;
            const __half* src = qkv + (size_t)(b * S_ + kt * 128 + r) * 1536 + D_ + h * 64 + d0;
            *(uint4*)(kv + r * 72 + d0) = *(const uint4*)src;
        }
        __syncthreads();

        float acc[4][4];
#pragma unroll
        for (int nt = 0; nt < 4; nt++)
#pragma unroll
            for (int j = 0; j < 4; j++) acc[nt][j] = 0.f;

#pragma unroll
        for (int ks = 0; ks < 4; ks++) {
            uint32_t afr[4];
            LDSM_X4(afr[0], afr[1], afr[2], afr[3], qa_addr + (uint32_t)(ks * 16) * 2);
            uint32_t bfr[4][2];
#pragma unroll
            for (int p = 0; p < 2; p++)
                LDSM_X4(bfr[2 * p][0], bfr[2 * p][1], bfr[2 * p + 1][0], bfr[2 * p + 1][1],
                        kb_addr + (uint32_t)(p * 16 * 72 + ks * 16) * 2);
#pragma unroll
            for (int nt = 0; nt < 4; nt++)
                mma_f16(acc[nt], afr, bfr[nt]);
        }
#pragma unroll
        for (int nt = 0; nt < 4; nt++) {
            const int col = kt * 128 + wn * 32 + nt * 8 + 2 * t4;
            const int row = wm * 16 + g;
            *(float2*)&sc[row * FA_SS + col]       = make_float2(acc[nt][0], acc[nt][1]);
            *(float2*)&sc[(row + 8) * FA_SS + col] = make_float2(acc[nt][2], acc[nt][3]);
        }
    }
    __syncthreads();

#pragma unroll
    for (int rr = 0; rr < 4; rr++) {
        const int row = wid * 4 + rr;
        float vals[16];
        float sum = 0.f;
#pragma unroll
        for (int t = 0; t < 4; t++) {
            const float4 v = *(const float4*)&sc[row * FA_SS + lane * 4 + t * 128];
            vals[t * 4 + 0] = fast_exp(v.x);
            vals[t * 4 + 1] = fast_exp(v.y);
            vals[t * 4 + 2] = fast_exp(v.z);
            vals[t * 4 + 3] = fast_exp(v.w);
            sum += vals[t * 4 + 0] + vals[t * 4 + 1] + vals[t * 4 + 2] + vals[t * 4 + 3];
        }
#pragma unroll
        for (int o = 16; o > 0; o >>= 1)
            sum += __shfl_xor_sync(0xFFFFFFFFu, sum, o);
        const float inv = 1.f / sum;
        float* prow = probs + ((size_t)bh * S_ + q0 + row) * S_;
        __half* phrow = (__half*)((char*)sc + row * FA_PH_B);
#pragma unroll
        for (int t = 0; t < 4; t++) {
            const int c = lane * 4 + t * 128;
            const __half2 h0 = __floats2half2_rn(vals[t * 4 + 0] * inv, vals[t * 4 + 1] * inv);
            const __half2 h1 = __floats2half2_rn(vals[t * 4 + 2] * inv, vals[t * 4 + 3] * inv);
            *(__half2*)&phrow[c]     = h0;
            *(__half2*)&phrow[c + 2] = h1;
            float4 o;
            o.x = __half2float(__low2half(h0));
            o.y = __half2float(__high2half(h0));
            o.z = __half2float(__low2half(h1));
            o.w = __half2float(__high2half(h1));
            *(float4*)&prow[c] = o;
        }
    }

    float pacc[2][4];
#pragma unroll
    for (int nt = 0; nt < 2; nt++)
#pragma unroll
        for (int j = 0; j < 4; j++) pacc[nt][j] = 0.f;

    for (int vt = 0; vt < 4; vt++) {
        __syncthreads();
#pragma unroll
        for (int i = 0; i < 4; i++) {
            const int idx = i * 256 + tid;
            const int r = idx >> 3;
            const int d0 = (idx & 7) * 8;
            const __half* src = qkv + (size_t)(b * S_ + vt * 128 + r) * 1536 + 2 * D_ + h * 64 + d0;
            *(uint4*)(kv + r * 72 + d0) = *(const uint4*)src;
        }
        __syncthreads();

#pragma unroll
        for (int ks = 0; ks < 8; ks++) {
            uint32_t afr[4];
            LDSM_X4(afr[0], afr[1], afr[2], afr[3],
                    pa_addr + (uint32_t)(vt * 128 + ks * 16) * 2);
            uint32_t bfr[2][2];
            LDSM_X4_T(bfr[0][0], bfr[0][1], bfr[1][0], bfr[1][1],
                      vb_addr + (uint32_t)(ks * 16 * 72) * 2);
            mma_f16(pacc[0], afr, bfr[0]);
            mma_f16(pacc[1], afr, bfr[1]);
        }
    }

#pragma unroll
    for (int nt = 0; nt < 2; nt++) {
        const int row = b * S_ + q0 + wm * 16 + g;
        const int col = h * 64 + wn * 16 + nt * 8 + 2 * t4;
        *(__half2*)&ctxh[(size_t)row * D_ + col] =
            __floats2half2_rn(pacc[nt][0], pacc[nt][1]);
        *(__half2*)&ctxh[(size_t)(row + 8) * D_ + col] =
            __floats2half2_rn(pacc[nt][2], pacc[nt][3]);
    }
}

// ---------------- SIMT GEMM (input proj / head1) ----------------
template <int ACT>
__global__ __launch_bounds__(256)
void gemm_kernel(const float* __restrict__ A, const float* __restrict__ W,
                 const float* __restrict__ bias, float* __restrict__ C,
                 __half* __restrict__ CH,
                 int M, int N, int K, const float* __restrict__ pe)
{
    __shared__ __align__(16) float As[8][128];
    __shared__ __align__(16) float Ws[8][128];

    const int tid = threadIdx.x;
    const int tx = tid & 15;
    const int ty = tid >> 4;
    const int m0 = blockIdx.y * 128;
    const int n0 = blockIdx.x * 128;

    float acc[2][2][4][4];
#pragma unroll
    for (int p = 0; p < 2; p++)
#pragma unroll
        for (int q = 0; q < 2; q++)
#pragma unroll
            for (int i = 0; i < 4; i++)
#pragma unroll
                for (int j = 0; j < 4; j++) acc[p][q][i][j] = 0.f;

    const int lr = tid >> 1;
    const int lk = (tid & 1) * 4;
    const float* Ag = A + (size_t)(m0 + lr) * K + lk;
    const float* Wg = W + (size_t)(n0 + lr) * K + lk;
    const bool aval = (m0 + lr) < M;

    for (int k0 = 0; k0 < K; k0 += 8) {
        float4 av = make_float4(0.f, 0.f, 0.f, 0.f);
        if (aval) av = *(const float4*)(Ag + k0);
        const float4 wv = *(const float4*)(Wg + k0);
        __syncthreads();
        As[lk + 0][lr] = av.x; As[lk + 1][lr] = av.y;
        As[lk + 2][lr] = av.z; As[lk + 3][lr] = av.w;
        Ws[lk + 0][lr] = wv.x; Ws[lk + 1][lr] = wv.y;
        Ws[lk + 2][lr] = wv.z; Ws[lk + 3][lr] = wv.w;
        __syncthreads();
#pragma unroll
        for (int kk = 0; kk < 8; kk++) {
            const float4 a0 = *(const float4*)&As[kk][ty * 4];
            const float4 a1 = *(const float4*)&As[kk][64 + ty * 4];
            const float4 b0 = *(const float4*)&Ws[kk][tx * 4];
            const float4 b1 = *(const float4*)&Ws[kk][64 + tx * 4];
            const float ar[2][4] = {{a0.x, a0.y, a0.z, a0.w}, {a1.x, a1.y, a1.z, a1.w}};
            const float br[2][4] = {{b0.x, b0.y, b0.z, b0.w}, {b1.x, b1.y, b1.z, b1.w}};
#pragma unroll
            for (int p = 0; p < 2; p++)
#pragma unroll
                for (int q = 0; q < 2; q++)
#pragma unroll
                    for (int i = 0; i < 4; i++)
#pragma unroll
                        for (int j = 0; j < 4; j++)
                            acc[p][q][i][j] += ar[p][i] * br[q][j];
        }
    }

#pragma unroll
    for (int p = 0; p < 2; p++) {
#pragma unroll
        for (int i = 0; i < 4; i++) {
            const int m = m0 + p * 64 + ty * 4 + i;
            if (m >= M) continue;
#pragma unroll
            for (int q = 0; q < 2; q++) {
                const int c = n0 + q * 64 + tx * 4;
                float4 o;
                float* po = &o.x;
#pragma unroll
                for (int j = 0; j < 4; j++) {
                    float v = acc[p][q][i][j] + bias[c + j];
                    if (ACT == 1) {
                        v = gelu_exact(v);
                    } else if (ACT == 2) {
                        v += pe[(m & (S_ - 1)) * D_ + c + j];
                    }
                    po[j] = v;
                }
                *(float4*)&C[(size_t)m * N + c] = o;
                if (ACT == 2) {
                    __half2* hd = (__half2*)&CH[(size_t)m * N + c];
                    hd[0] = __floats2half2_rn(o.x, o.y);
                    hd[1] = __floats2half2_rn(o.z, o.w);
                }
            }
        }
    }
}

// ---------------- fused residual-add + LayerNorm (fp32 + fp16 outputs) ----------------
__global__ __launch_bounds__(128)
void ln_kernel(const float* __restrict__ x, const float* __restrict__ add,
               const float* __restrict__ w, const float* __restrict__ bvec,
               float* __restrict__ out, __half* __restrict__ outh)
{
    const int row = blockIdx.x;
    const int tid = threadIdx.x;
    const float* xr = x + (size_t)row * D_;
    const float* ar = add + (size_t)row * D_;
    float v[4];
    float s = 0.f;
#pragma unroll
    for (int i = 0; i < 4; i++) {
        const int c = tid + i * 128;
        v[i] = xr[c] + ar[c];
        s += v[i];
    }
    __shared__ float red[4];
#pragma unroll
    for (int o = 16; o > 0; o >>= 1) s += __shfl_xor_sync(0xFFFFFFFFu, s, o);
    if ((tid & 31) == 0) red[tid >> 5] = s;
    __syncthreads();
    const float mean = (red[0] + red[1] + red[2] + red[3]) * (1.f / 512.f);
    float vs = 0.f;
#pragma unroll
    for (int i = 0; i < 4; i++) {
        const float d = v[i] - mean;
        vs += d * d;
    }
    __syncthreads();
#pragma unroll
    for (int o = 16; o > 0; o >>= 1) vs += __shfl_xor_sync(0xFFFFFFFFu, vs, o);
    if ((tid & 31) == 0) red[tid >> 5] = vs;
    __syncthreads();
    const float rstd = rsqrtf((red[0] + red[1] + red[2] + red[3]) * (1.f / 512.f) + 1e-5f);
    float* orow = out + (size_t)row * D_;
    __half* hrow = outh + (size_t)row * D_;
#pragma unroll
    for (int i = 0; i < 4; i++) {
        const int c = tid + i * 128;
        const float val = (v[i] - mean) * rstd * w[c] + bvec[c];
        orow[c] = val;
        hrow[c] = __float2half_rn(val);
    }
}

// ---------------- mean+max pooling over sequence ----------------
__global__ __launch_bounds__(512)
void pool_kernel(const float* __restrict__ x, float* __restrict__ pool)
{
    const int b = blockIdx.x, d = threadIdx.x;
    float s = 0.f, m = -1e30f;
    for (int t = 0; t < S_; t++) {
        const float v = x[(size_t)(b * S_ + t) * D_ + d];
        s += v;
        m = fmaxf(m, v);
    }
    pool[b * (2 * D_) + d] = s * (1.f / 512.f);
    pool[b * (2 * D_) + D_ + d] = m;
}

// ---------------- final head ----------------
__global__ __launch_bounds__(128)
void head2_kernel(const float* __restrict__ h, const float* __restrict__ w,
                  const float* __restrict__ bb, float* __restrict__ out)
{
    const int b = blockIdx.x, tid = threadIdx.x;
    float s = 0.f;
    for (int c = tid; c < D_; c += 128) s += h[(size_t)b * D_ + c] * w[c];
    __shared__ float red[4];
#pragma unroll
    for (int o = 16; o > 0; o >>= 1) s += __shfl_xor_sync(0xFFFFFFFFu, s, o);
    if ((tid & 31) == 0) red[tid >> 5] = s;
    __syncthreads();
    if (tid == 0) out[b] = red[0] + red[1] + red[2] + red[3] + bb[0];
}

// ---------------- launch ----------------
extern "C" void kernel_launch(void* const* d_in, const int* in_sizes, int n_in,
                              void* d_out, int out_size)
{
    const float* x_in = (const float*)d_in[0];
    const float* w_in = (const float*)d_in[1];
    const float* b_in = (const float*)d_in[2];
    const float* inpw = (const float*)d_in[3];
    const float* inpb = (const float*)d_in[4];
    const float* outw = (const float*)d_in[5];
    const float* outb = (const float*)d_in[6];
    const float* ln1w = (const float*)d_in[7];
    const float* ln1b = (const float*)d_in[8];
    const float* ln2w = (const float*)d_in[9];
    const float* ln2b = (const float*)d_in[10];
    const float* ff1w = (const float*)d_in[11];
    const float* ff1b = (const float*)d_in[12];
    const float* ff2w = (const float*)d_in[13];
    const float* ff2b = (const float*)d_in[14];
    const float* h1w  = (const float*)d_in[15];
    const float* h1b  = (const float*)d_in[16];
    const float* h2w  = (const float*)d_in[17];
    const float* h2b  = (const float*)d_in[18];

    float* out  = (float*)d_out;
    float* attn = out + 32;   // [L,B,H,S,S] follows the [B,1] output

    float *px, *ptmp, *ppool, *phead, *ppe;
    __half *pxh, *pqkvh, *pctxh, *pffh, *pwbh;
    cudaGetSymbolAddress((void**)&px,    g_x);
    cudaGetSymbolAddress((void**)&pxh,   g_xh);
    cudaGetSymbolAddress((void**)&pqkvh, g_qkvh);
    cudaGetSymbolAddress((void**)&pctxh, g_ctxh);
    cudaGetSymbolAddress((void**)&ptmp,  g_tmp);
    cudaGetSymbolAddress((void**)&pffh,  g_ffh);
    cudaGetSymbolAddress((void**)&ppool, g_pool);
    cudaGetSymbolAddress((void**)&phead, g_head);
    cudaGetSymbolAddress((void**)&pwbh,  g_wbufh);
    cudaGetSymbolAddress((void**)&ppe,   g_pe);

    cudaFuncSetAttribute(gemm_h<0,2>, cudaFuncAttributeMaxDynamicSharedMemorySize, MH_SMEM);
    cudaFuncSetAttribute(gemm_h<0,0>, cudaFuncAttributeMaxDynamicSharedMemorySize, MH_SMEM);
    cudaFuncSetAttribute(gemm_h<1,2>, cudaFuncAttributeMaxDynamicSharedMemorySize, MH_SMEM);
    cudaFuncSetAttribute(fused_attn, cudaFuncAttributeMaxDynamicSharedMemorySize, FA_SMEM_BYTES);

    const dim3 blk(256);
    const dim3 mblk(128);

    // per-replay setup: fp16 weights + PE table
    round_all<<<(WB_TOT + 1023) / 1024, 256>>>(inpw, outw, ff1w, ff2w, pwbh);
    pe_init<<<(S_ * D_) / 256, 256>>>(ppe);

    // input projection + PE (SIMT; fp32 residual + fp16 GEMM copy)
    gemm_kernel<2><<<dim3(D_ / 128, TOK_ / 128), blk>>>(
        x_in, w_in, b_in, px, pxh, TOK_, D_, IN_, ppe);

    for (int l = 0; l < L_; l++) {
        // QKV projection (fp16 in, fp16 out -> attention)
        gemm_h<0,2><<<dim3((3 * D_) / 128, TOK_ / 128), mblk, MH_SMEM>>>(
            pxh, pwbh + WB_IN + (size_t)l * 3 * D_ * D_, inpb + l * 3 * D_,
            nullptr, pqkvh, TOK_, 3 * D_, D_);

        float* attn_l = attn + (size_t)l * B_ * H_ * S_ * S_;

        // fused scores + softmax + probs-out + P@V (all fp16 mma)
        fused_attn<<<dim3(S_ / 32, B_ * H_), blk, FA_SMEM_BYTES>>>(pqkvh, attn_l, pctxh);

        // output projection (fp16 in, fp32 out -> LN)
        gemm_h<0,0><<<dim3(D_ / 128, TOK_ / 128), mblk, MH_SMEM>>>(
            pctxh, pwbh + WB_OUT + (size_t)l * D_ * D_, outb + l * D_,
            ptmp, nullptr, TOK_, D_, D_);

        ln_kernel<<<TOK_, 128>>>(px, ptmp, ln1w + l * D_, ln1b + l * D_, px, pxh);

        // ff1 + GELU (fp16 in, fp16 out -> ff2)
        gemm_h<1,2><<<dim3(FF_ / 128, TOK_ / 128), mblk, MH_SMEM>>>(
            pxh, pwbh + WB_FF1 + (size_t)l * FF_ * D_, ff1b + l * FF_,
            nullptr, pffh, TOK_, FF_, D_);

        // ff2 (fp16 in, fp32 out -> LN)
        gemm_h<0,0><<<dim3(D_ / 128, TOK_ / 128), mblk, MH_SMEM>>>(
            pffh, pwbh + WB_FF2 + (size_t)l * D_ * FF_, ff2b + l * D_,
            ptmp, nullptr, TOK_, D_, FF_);

        ln_kernel<<<TOK_, 128>>>(px, ptmp, ln2w + l * D_, ln2b + l * D_, px, pxh);
    }

    pool_kernel<<<B_, 512>>>(px, ppool);
    gemm_kernel<1><<<dim3(D_ / 128, 1), blk>>>(
        ppool, h1w, h1b, phead, nullptr, B_, D_, 2 * D_, ppe);
    head2_kernel<<<B_, 128>>>(phead, h2w, h2b, out);
}